// round 5
// baseline (speedup 1.0000x reference)
#include <cuda_runtime.h>

// ---------------- problem constants (fixed shapes) ----------------
#define C_CLASSES   12
#define LOG_DHW     20                    // d*h*w = 64*128*128 = 2^20
#define DHW         (1u << LOG_DHW)
#define NPIX        (2u * DHW)            // 2,097,152
#define NPIX4       (NPIX / 4u)           // 524,288 uint4
#define MIN_KEPT_K  10000u
#define IGNORE_LBL  255
#define INF_BITS    0x7F800000u
#define B09_BITS    0x3F666666u           // bits of 0.9f (probs >= 0: uint order == float order)

#define BLOCK_THREADS 256

// ---------------- device scratch ----------------
__device__ unsigned int g_prob_bits[NPIX];   // prob-at-label bits; INF for invalid
__device__ unsigned int g_buf[NPIX];         // compacted elements of L0 bin b0
__device__ unsigned int g_hist[1024];        // L0 histogram of bits>>21
__device__ unsigned int g_bufcnt;
__device__ double       g_sumAll, g_sumB, g_sumL;
__device__ unsigned int g_cntAll, g_cntB, g_cntL;
__device__ unsigned int g_bar_count;         // software grid barrier (self-resetting)
__device__ unsigned int g_bar_gen;

// ---------------- software grid barrier (uses gridDim.x) ----------------
__device__ __forceinline__ void grid_barrier() {
    __syncthreads();
    __threadfence();                                  // release
    if (threadIdx.x == 0) {
        unsigned gen = *(volatile unsigned*)&g_bar_gen;
        unsigned a   = atomicAdd(&g_bar_count, 1u);
        if (a == gridDim.x - 1u) {
            *(volatile unsigned*)&g_bar_count = 0u;
            __threadfence();
            atomicAdd(&g_bar_gen, 1u);
        } else {
            while (*(volatile unsigned*)&g_bar_gen == gen) { }
        }
        __threadfence();                              // acquire
    }
    __syncthreads();
}

// ---------------- shared memory layout ----------------
// [0:64)          header: H[0]=b0 H[1]=r H[2]=keep_all H[3]=resBin H[4]=resRank
//                         H[5]=accC HF[6]=accS HF[7]=sumBelow1 H[8]=cntBelow1
// [64:8256)       phase1 hist (1024 u32) / finalize cnt (2048 u32) / reduce arrays
// [8256:16448)    finalize sum (2048 f32)
// [16448:17472)   scan (256 u32)
#define SMEM_BYTES 17472

__global__ void __launch_bounds__(BLOCK_THREADS)
ohem_kernel(const float* __restrict__ pred, const int* __restrict__ tgt,
            float* __restrict__ out) {
    __shared__ __align__(16) unsigned char S[SMEM_BYTES];
    unsigned* H  = (unsigned*)S;
    float*    HF = (float*)S;
    const int t    = threadIdx.x;
    const int bid  = blockIdx.x;
    const int lane = t & 31;
    const unsigned NTH = gridDim.x * BLOCK_THREADS;

    // ===== phase 0: block 0 zeros globals (ordered before use by the phase-1 barrier) =====
    if (bid == 0) {
        for (int i = t; i < 1024; i += BLOCK_THREADS) g_hist[i] = 0u;
        if (t == 0) {
            g_bufcnt = 0u;
            g_sumAll = 0.0; g_sumB = 0.0; g_sumL = 0.0;
            g_cntAll = 0u;  g_cntB = 0u;  g_cntL = 0u;
        }
    }

    // ===== phase 1: streaming map (1 pixel/thread) + warp-aggregated L0 hist =====
    {
        unsigned* sh = (unsigned*)(S + 64);
        for (int i = t; i < 1024; i += BLOCK_THREADS) sh[i] = 0u;
        __syncthreads();

        for (unsigned p = bid * BLOCK_THREADS + t; p < NPIX; p += NTH) {
            unsigned n = p >> LOG_DHW;
            unsigned s = p & (DHW - 1u);
            const float* base = pred + (((size_t)n * C_CLASSES) << LOG_DHW) + s;

            float v[C_CLASSES];
#pragma unroll
            for (int c = 0; c < C_CLASSES; c++)
                v[c] = __ldcs(base + ((size_t)c << LOG_DHW));
            int l = __ldcs(tgt + p);

            float m = v[0];
#pragma unroll
            for (int c = 1; c < C_CLASSES; c++) m = fmaxf(m, v[c]);
            float sum = 0.f, xl = 0.f;
#pragma unroll
            for (int c = 0; c < C_CLASSES; c++) {
                sum += __expf(v[c] - m);
                if (c == l) xl = v[c];
            }
            float lp = xl - (m + __logf(sum));
            unsigned b = (l == IGNORE_LBL) ? INF_BITS
                                           : __float_as_uint(__expf(lp));
            g_prob_bits[p] = b;

            // warp-aggregated shared histogram update
            unsigned bin  = b >> 21;
            unsigned mask = __match_any_sync(0xFFFFFFFFu, bin);
            if ((unsigned)lane == (unsigned)(__ffs(mask) - 1))
                atomicAdd(&sh[bin], (unsigned)__popc(mask));
        }
        __syncthreads();
        for (int i = t; i < 1024; i += BLOCK_THREADS) {
            unsigned c = sh[i];
            if (c) atomicAdd(&g_hist[i], c);
        }
    }
    grid_barrier();

    // ===== phase 2: every block locates kth L0 bin (hist is L2-resident) =====
    {
        unsigned* scanS = (unsigned*)(S + 16448);
        unsigned inv       = g_hist[1020];                 // INF_BITS>>21 = 1020
        unsigned num_valid = NPIX - inv;
        unsigned keep_all  = (MIN_KEPT_K >= num_valid) ? 1u : 0u;
        unsigned mk        = (MIN_KEPT_K < num_valid) ? MIN_KEPT_K : num_valid;
        unsigned k         = (mk > 0u) ? (mk - 1u) : 0u;

        unsigned h[4], local = 0u;
#pragma unroll
        for (int i = 0; i < 4; i++) { h[i] = g_hist[t * 4 + i]; local += h[i]; }
        scanS[t] = local;
        __syncthreads();
        for (int off = 1; off < BLOCK_THREADS; off <<= 1) {
            unsigned add = (t >= off) ? scanS[t - off] : 0u;
            __syncthreads();
            scanS[t] += add;
            __syncthreads();
        }
        unsigned incl = scanS[t], excl = incl - local;
        if (k >= excl && k < incl) {
            unsigned run = excl;
            bool found = false;
#pragma unroll
            for (int i = 0; i < 4; i++) {
                if (!found) {
                    if (k < run + h[i]) { H[0] = t * 4 + i; H[1] = k - run; found = true; }
                    else run += h[i];
                }
            }
        }
        if (t == 0) H[2] = keep_all;
        __syncthreads();
    }

    // ===== phase 3: fused partial sums + boundary-bin compaction (prob_bits from L2) =====
    {
        const unsigned b0 = H[0];
        float    sAll = 0.f, sB = 0.f, sL = 0.f;
        unsigned cAll = 0u,  cB = 0u,  cL = 0u;

        for (unsigned i = bid * BLOCK_THREADS + t; i < NPIX4; i += NTH) {
            uint4 pb = ((const uint4*)g_prob_bits)[i];
            unsigned bs[4] = { pb.x, pb.y, pb.z, pb.w };
#pragma unroll
            for (int j = 0; j < 4; j++) {
                unsigned b = bs[j];
                if (b != INF_BITS) {
                    float nll = -__logf(__uint_as_float(b));
                    cAll++; sAll += nll;
                    if (b <= B09_BITS) { cB++; sB += nll; }
                    unsigned bin = b >> 21;
                    if (bin < b0)       { cL++; sL += nll; }
                    else if (bin == b0) { g_buf[atomicAdd(&g_bufcnt, 1u)] = b; }
                }
            }
        }

#pragma unroll
        for (int off = 16; off > 0; off >>= 1) {
            sAll += __shfl_down_sync(0xFFFFFFFFu, sAll, off);
            sB   += __shfl_down_sync(0xFFFFFFFFu, sB,   off);
            sL   += __shfl_down_sync(0xFFFFFFFFu, sL,   off);
            cAll += __shfl_down_sync(0xFFFFFFFFu, cAll, off);
            cB   += __shfl_down_sync(0xFFFFFFFFu, cB,   off);
            cL   += __shfl_down_sync(0xFFFFFFFFu, cL,   off);
        }
        float*    ws = (float*)(S + 64);
        unsigned* wc = (unsigned*)(S + 64 + 96);
        int w = t >> 5;
        if (lane == 0) {
            ws[w] = sAll; ws[8 + w] = sB; ws[16 + w] = sL;
            wc[w] = cAll; wc[8 + w] = cB; wc[16 + w] = cL;
        }
        __syncthreads();
        if (t == 0) {
            float    SA = 0.f, SBs = 0.f, SL = 0.f;
            unsigned CA = 0u,  CBc = 0u, CL = 0u;
#pragma unroll
            for (int i = 0; i < 8; i++) {
                SA += ws[i]; SBs += ws[8 + i]; SL += ws[16 + i];
                CA += wc[i]; CBc += wc[8 + i]; CL += wc[16 + i];
            }
            atomicAdd(&g_sumAll, (double)SA);
            atomicAdd(&g_sumB,   (double)SBs);
            atomicAdd(&g_sumL,   (double)SL);
            atomicAdd(&g_cntAll, CA);
            atomicAdd(&g_cntB,   CBc);
            atomicAdd(&g_cntL,   CL);
        }
    }
    grid_barrier();

    // ===== phase 4: finalize (block 0 only) =====
    if (bid != 0) return;
    {
        unsigned* cnt   = (unsigned*)(S + 64);        // 2048
        float*    sum   = (float*)(S + 64 + 8192);    // 2048
        unsigned* scanS = (unsigned*)(S + 16448);     // 256
        const unsigned keep_all = H[2];
        const unsigned b0 = H[0];
        const unsigned r  = H[1];
        const unsigned M  = g_bufcnt;

        // ---- round 1: mid 11 bits ----
        for (int i = t; i < 2048; i += BLOCK_THREADS) { cnt[i] = 0u; sum[i] = 0.f; }
        if (t == 0) { H[3] = 0u; H[4] = 0u; H[5] = 0u; HF[6] = 0.f; }
        __syncthreads();
        for (unsigned i = t; i < M; i += BLOCK_THREADS) {
            unsigned b = g_buf[i];
            unsigned mid = (b >> 10) & 0x7FFu;
            atomicAdd(&cnt[mid], 1u);
            atomicAdd(&sum[mid], -__logf(__uint_as_float(b)));
        }
        __syncthreads();
        {
            unsigned h[8], local = 0u;
#pragma unroll
            for (int j = 0; j < 8; j++) { h[j] = cnt[t * 8 + j]; local += h[j]; }
            scanS[t] = local;
            __syncthreads();
            for (int off = 1; off < BLOCK_THREADS; off <<= 1) {
                unsigned add = (t >= off) ? scanS[t - off] : 0u;
                __syncthreads();
                scanS[t] += add;
                __syncthreads();
            }
            unsigned incl = scanS[t], excl = incl - local;
            if (r >= excl && r < incl) {
                unsigned run = excl;
                bool found = false;
#pragma unroll
                for (int j = 0; j < 8; j++) {
                    if (!found) {
                        if (r < run + h[j]) { H[3] = t * 8 + j; H[4] = r - run; found = true; }
                        else run += h[j];
                    }
                }
            }
            __syncthreads();
            unsigned b1 = H[3];
            float    s = 0.f; unsigned c = 0u;
#pragma unroll
            for (int j = 0; j < 8; j++)
                if ((unsigned)(t * 8 + j) < b1) { s += sum[t * 8 + j]; c += h[j]; }
            atomicAdd(&HF[6], s); atomicAdd(&H[5], c);
            __syncthreads();
            if (t == 0) { HF[7] = HF[6]; H[8] = H[5]; }   // sumBelow1 / cntBelow1
            __syncthreads();
        }
        const unsigned b1 = H[3], r2 = H[4];

        // ---- round 2: low 10 bits within (b0, b1) ----
        for (int i = t; i < 1024; i += BLOCK_THREADS) { cnt[i] = 0u; sum[i] = 0.f; }
        if (t == 0) { H[3] = 0u; H[5] = 0u; HF[6] = 0.f; }
        __syncthreads();
        for (unsigned i = t; i < M; i += BLOCK_THREADS) {
            unsigned b = g_buf[i];
            if (((b >> 10) & 0x7FFu) == b1) {
                unsigned low = b & 0x3FFu;
                atomicAdd(&cnt[low], 1u);
                atomicAdd(&sum[low], -__logf(__uint_as_float(b)));
            }
        }
        __syncthreads();
        {
            unsigned h[4], local = 0u;
#pragma unroll
            for (int j = 0; j < 4; j++) { h[j] = cnt[t * 4 + j]; local += h[j]; }
            scanS[t] = local;
            __syncthreads();
            for (int off = 1; off < BLOCK_THREADS; off <<= 1) {
                unsigned add = (t >= off) ? scanS[t - off] : 0u;
                __syncthreads();
                scanS[t] += add;
                __syncthreads();
            }
            unsigned incl = scanS[t], excl = incl - local;
            if (r2 >= excl && r2 < incl) {
                unsigned run = excl;
                bool found = false;
#pragma unroll
                for (int j = 0; j < 4; j++) {
                    if (!found) {
                        if (r2 < run + h[j]) { H[3] = t * 4 + j; found = true; }
                        else run += h[j];
                    }
                }
            }
            __syncthreads();
            unsigned b2 = H[3];
            float    s = 0.f; unsigned c = 0u;
#pragma unroll
            for (int j = 0; j < 4; j++)
                if ((unsigned)(t * 4 + j) <= b2) { s += sum[t * 4 + j]; c += h[j]; }   // ties kept
            atomicAdd(&HF[6], s); atomicAdd(&H[5], c);
            __syncthreads();

            if (t == 0) {
                float    sumBound = HF[7] + HF[6];
                unsigned cntBound = H[8] + H[5];
                unsigned kth_bits = (b0 << 21) | (b1 << 10) | b2;
                double   num; unsigned cntk;
                if (keep_all)                  { num = g_sumAll;                  cntk = g_cntAll; }
                else if (kth_bits <= B09_BITS) { num = g_sumB;                    cntk = g_cntB;   }  // threshold = 0.9
                else                           { num = g_sumL + (double)sumBound; cntk = g_cntL + cntBound; }
                unsigned denom = (cntk > 0u) ? cntk : 1u;
                out[0] = (float)(num / (double)denom);
            }
        }
    }
}

// ---------------- launch ----------------
extern "C" void kernel_launch(void* const* d_in, const int* in_sizes, int n_in,
                              void* d_out, int out_size) {
    const float* pred = (const float*)d_in[0];
    const int*   tgt  = (const int*)d_in[1];
    float*       out  = (float*)d_out;

    int dev = 0, sms = 148, nb = 1;
    cudaGetDevice(&dev);
    cudaDeviceGetAttribute(&sms, cudaDevAttrMultiProcessorCount, dev);
    cudaOccupancyMaxActiveBlocksPerMultiprocessor(&nb, ohem_kernel, BLOCK_THREADS, 0);
    if (nb < 1) nb = 1;
    int grid = sms * nb;                 // guaranteed co-resident -> barrier is safe

    ohem_kernel<<<grid, BLOCK_THREADS>>>(pred, tgt, out);
}

// round 6
// speedup vs baseline: 1.0335x; 1.0335x over previous
#include <cuda_runtime.h>

// ---------------- problem constants (fixed shapes) ----------------
#define C_CLASSES   12
#define LOG_DHW     20                    // d*h*w = 64*128*128 = 2^20
#define DHW         (1u << LOG_DHW)
#define NPIX        (2u * DHW)            // 2,097,152
#define NPIX4       (NPIX / 4u)           // 524,288 uint4 groups
#define MIN_KEPT_K  10000u
#define IGNORE_LBL  255
#define INF_BITS    0x7F800000u
#define B09_BITS    0x3F666666u           // bits of 0.9f (probs >= 0: uint order == float order)

// ---------------- device scratch (zero-init; every run restores zeros) ----------------
__device__ unsigned int g_prob_bits[NPIX];   // prob-at-label bits; INF for invalid
__device__ unsigned int g_buf[NPIX];         // compacted elements of L0 bin b0
__device__ unsigned int g_hist[1024];        // L0 histogram of bits>>21
__device__ unsigned int g_bufcnt;
__device__ double       g_sumAll, g_sumB, g_sumL;
__device__ unsigned int g_cntAll, g_cntB, g_cntL;
__device__ unsigned int g_bar_count;         // self-resetting grid barrier
__device__ unsigned int g_bar_gen;           // monotonic generation

// ==================================================================
// Kernel 1: straight-line CE map + L0 histogram.
// 2048 blocks x 256 threads: each thread handles EXACTLY one uint4
// pixel-group (4 px). 12 consecutive float4 loads -> deep MLP.
// ==================================================================
#define K1_THREADS 256
#define K1_BLOCKS  (NPIX4 / K1_THREADS)   // 2048

__device__ __forceinline__ unsigned int pixel_prob_bits(const float v[C_CLASSES], int l) {
    float m = v[0];
#pragma unroll
    for (int c = 1; c < C_CLASSES; c++) m = fmaxf(m, v[c]);
    float sum = 0.f, xl = 0.f;
#pragma unroll
    for (int c = 0; c < C_CLASSES; c++) {
        sum += __expf(v[c] - m);
        if (c == l) xl = v[c];
    }
    float lp = xl - (m + __logf(sum));
    if (l == IGNORE_LBL) return INF_BITS;      // invalid -> +inf (sorts last, like reference)
    return __float_as_uint(__expf(lp));        // prob in [0,1]
}

__global__ void __launch_bounds__(K1_THREADS)
compute_kernel(const float* __restrict__ pred, const int* __restrict__ tgt) {
    __shared__ unsigned int sh[1024];
    const int t = threadIdx.x;
    for (int i = t; i < 1024; i += K1_THREADS) sh[i] = 0u;
    __syncthreads();

    const unsigned p4 = blockIdx.x * K1_THREADS + t;      // uint4-group index
    const unsigned n  = p4 >> 18;                         // DHW/4 = 2^18 groups per image
    const unsigned s4 = p4 & 0x3FFFFu;
    const float4* base = (const float4*)(pred + (((size_t)n * C_CLASSES) << LOG_DHW)) + s4;

    float4 x[C_CLASSES];
#pragma unroll
    for (int c = 0; c < C_CLASSES; c++)
        x[c] = base[(size_t)c << 18];

    int4 lab = ((const int4*)tgt)[p4];                    // target is int32 (jax x64 disabled)

    float v[C_CLASSES];
    uint4 pb;
#pragma unroll
    for (int c = 0; c < C_CLASSES; c++) v[c] = x[c].x;
    pb.x = pixel_prob_bits(v, lab.x);
#pragma unroll
    for (int c = 0; c < C_CLASSES; c++) v[c] = x[c].y;
    pb.y = pixel_prob_bits(v, lab.y);
#pragma unroll
    for (int c = 0; c < C_CLASSES; c++) v[c] = x[c].z;
    pb.z = pixel_prob_bits(v, lab.z);
#pragma unroll
    for (int c = 0; c < C_CLASSES; c++) v[c] = x[c].w;
    pb.w = pixel_prob_bits(v, lab.w);

    ((uint4*)g_prob_bits)[p4] = pb;

    atomicAdd(&sh[pb.x >> 21], 1u);
    atomicAdd(&sh[pb.y >> 21], 1u);
    atomicAdd(&sh[pb.z >> 21], 1u);
    atomicAdd(&sh[pb.w >> 21], 1u);

    __syncthreads();
    for (int i = t; i < 1024; i += K1_THREADS) {
        unsigned c = sh[i];
        if (c) atomicAdd(&g_hist[i], c);
    }
}

// ==================================================================
// Kernel 2: select + fused sums/compaction + finalize + state reset.
// Persistent, occupancy-sized grid; one internal grid barrier.
// ==================================================================
#define K2_THREADS 256

__device__ __forceinline__ void grid_barrier() {
    __syncthreads();
    __threadfence();                                  // release
    if (threadIdx.x == 0) {
        unsigned gen = *(volatile unsigned*)&g_bar_gen;
        unsigned a   = atomicAdd(&g_bar_count, 1u);
        if (a == gridDim.x - 1u) {
            *(volatile unsigned*)&g_bar_count = 0u;
            __threadfence();
            atomicAdd(&g_bar_gen, 1u);
        } else {
            while (*(volatile unsigned*)&g_bar_gen == gen) { }
        }
        __threadfence();                              // acquire
    }
    __syncthreads();
}

// shared layout:
// [0:64)        header: H[0]=b0 H[1]=r H[2]=keep_all H[3]=resBin H[4]=resRank
//                       H[5]=accC HF[6]=accS HF[7]=sumBelow1 H[8]=cntBelow1
// [64:8256)     cnt (2048 u32) / warp-reduce arrays
// [8256:16448)  sum (2048 f32)
// [16448:17472) scan (256 u32)
#define SMEM_BYTES 17472

__global__ void __launch_bounds__(K2_THREADS)
tail_kernel(float* __restrict__ out) {
    __shared__ __align__(16) unsigned char S[SMEM_BYTES];
    unsigned* H  = (unsigned*)S;
    float*    HF = (float*)S;
    const int t    = threadIdx.x;
    const int bid  = blockIdx.x;
    const int lane = t & 31;
    const unsigned NTH = gridDim.x * K2_THREADS;

    // ----- phase A: every block locates kth L0 bin (g_hist is L2-resident) -----
    {
        unsigned* scanS = (unsigned*)(S + 16448);
        unsigned inv       = g_hist[1020];                 // INF_BITS>>21 = 1020
        unsigned num_valid = NPIX - inv;
        unsigned keep_all  = (MIN_KEPT_K >= num_valid) ? 1u : 0u;
        unsigned mk        = (MIN_KEPT_K < num_valid) ? MIN_KEPT_K : num_valid;
        unsigned k         = (mk > 0u) ? (mk - 1u) : 0u;

        unsigned h[4], local = 0u;
#pragma unroll
        for (int i = 0; i < 4; i++) { h[i] = g_hist[t * 4 + i]; local += h[i]; }
        scanS[t] = local;
        __syncthreads();
        for (int off = 1; off < K2_THREADS; off <<= 1) {
            unsigned add = (t >= off) ? scanS[t - off] : 0u;
            __syncthreads();
            scanS[t] += add;
            __syncthreads();
        }
        unsigned incl = scanS[t], excl = incl - local;
        if (k >= excl && k < incl) {
            unsigned run = excl;
            bool found = false;
#pragma unroll
            for (int i = 0; i < 4; i++) {
                if (!found) {
                    if (k < run + h[i]) { H[0] = t * 4 + i; H[1] = k - run; found = true; }
                    else run += h[i];
                }
            }
        }
        if (t == 0) H[2] = keep_all;
        __syncthreads();
    }

    // ----- phase B: fused partial sums + boundary-bin compaction (prob_bits in L2) -----
    {
        const unsigned b0 = H[0];
        float    sAll = 0.f, sB = 0.f, sL = 0.f;
        unsigned cAll = 0u,  cB = 0u,  cL = 0u;

        for (unsigned i = bid * K2_THREADS + t; i < NPIX4; i += NTH) {
            uint4 pb = ((const uint4*)g_prob_bits)[i];
            unsigned bs[4] = { pb.x, pb.y, pb.z, pb.w };
#pragma unroll
            for (int j = 0; j < 4; j++) {
                unsigned b = bs[j];
                if (b != INF_BITS) {
                    float nll = -__logf(__uint_as_float(b));
                    cAll++; sAll += nll;
                    if (b <= B09_BITS) { cB++; sB += nll; }
                    unsigned bin = b >> 21;
                    if (bin < b0)       { cL++; sL += nll; }
                    else if (bin == b0) { g_buf[atomicAdd(&g_bufcnt, 1u)] = b; }
                }
            }
        }

#pragma unroll
        for (int off = 16; off > 0; off >>= 1) {
            sAll += __shfl_down_sync(0xFFFFFFFFu, sAll, off);
            sB   += __shfl_down_sync(0xFFFFFFFFu, sB,   off);
            sL   += __shfl_down_sync(0xFFFFFFFFu, sL,   off);
            cAll += __shfl_down_sync(0xFFFFFFFFu, cAll, off);
            cB   += __shfl_down_sync(0xFFFFFFFFu, cB,   off);
            cL   += __shfl_down_sync(0xFFFFFFFFu, cL,   off);
        }
        float*    ws = (float*)(S + 64);
        unsigned* wc = (unsigned*)(S + 64 + 96);
        int w = t >> 5;
        if (lane == 0) {
            ws[w] = sAll; ws[8 + w] = sB; ws[16 + w] = sL;
            wc[w] = cAll; wc[8 + w] = cB; wc[16 + w] = cL;
        }
        __syncthreads();
        if (t == 0) {
            float    SA = 0.f, SBs = 0.f, SL = 0.f;
            unsigned CA = 0u,  CBc = 0u, CL = 0u;
#pragma unroll
            for (int i = 0; i < 8; i++) {
                SA += ws[i]; SBs += ws[8 + i]; SL += ws[16 + i];
                CA += wc[i]; CBc += wc[8 + i]; CL += wc[16 + i];
            }
            atomicAdd(&g_sumAll, (double)SA);
            atomicAdd(&g_sumB,   (double)SBs);
            atomicAdd(&g_sumL,   (double)SL);
            atomicAdd(&g_cntAll, CA);
            atomicAdd(&g_cntB,   CBc);
            atomicAdd(&g_cntL,   CL);
        }
    }
    grid_barrier();

    // ----- phase C: finalize + state reset (block 0 only) -----
    if (bid != 0) return;
    {
        unsigned* cnt   = (unsigned*)(S + 64);        // 2048
        float*    sum   = (float*)(S + 64 + 8192);    // 2048
        unsigned* scanS = (unsigned*)(S + 16448);     // 256
        const unsigned keep_all = H[2];
        const unsigned b0 = H[0];
        const unsigned r  = H[1];
        const unsigned M  = g_bufcnt;

        // ---- round 1: mid 11 bits ----
        for (int i = t; i < 2048; i += K2_THREADS) { cnt[i] = 0u; sum[i] = 0.f; }
        if (t == 0) { H[3] = 0u; H[4] = 0u; H[5] = 0u; HF[6] = 0.f; }
        __syncthreads();
        for (unsigned i = t; i < M; i += K2_THREADS) {
            unsigned b = g_buf[i];
            unsigned mid = (b >> 10) & 0x7FFu;
            atomicAdd(&cnt[mid], 1u);
            atomicAdd(&sum[mid], -__logf(__uint_as_float(b)));
        }
        __syncthreads();
        {
            unsigned h[8], local = 0u;
#pragma unroll
            for (int j = 0; j < 8; j++) { h[j] = cnt[t * 8 + j]; local += h[j]; }
            scanS[t] = local;
            __syncthreads();
            for (int off = 1; off < K2_THREADS; off <<= 1) {
                unsigned add = (t >= off) ? scanS[t - off] : 0u;
                __syncthreads();
                scanS[t] += add;
                __syncthreads();
            }
            unsigned incl = scanS[t], excl = incl - local;
            if (r >= excl && r < incl) {
                unsigned run = excl;
                bool found = false;
#pragma unroll
                for (int j = 0; j < 8; j++) {
                    if (!found) {
                        if (r < run + h[j]) { H[3] = t * 8 + j; H[4] = r - run; found = true; }
                        else run += h[j];
                    }
                }
            }
            __syncthreads();
            unsigned b1 = H[3];
            float    s = 0.f; unsigned c = 0u;
#pragma unroll
            for (int j = 0; j < 8; j++)
                if ((unsigned)(t * 8 + j) < b1) { s += sum[t * 8 + j]; c += h[j]; }
            atomicAdd(&HF[6], s); atomicAdd(&H[5], c);
            __syncthreads();
            if (t == 0) { HF[7] = HF[6]; H[8] = H[5]; }   // sumBelow1 / cntBelow1
            __syncthreads();
        }
        const unsigned b1 = H[3], r2 = H[4];

        // ---- round 2: low 10 bits ----
        for (int i = t; i < 1024; i += K2_THREADS) { cnt[i] = 0u; sum[i] = 0.f; }
        if (t == 0) { H[3] = 0u; H[5] = 0u; HF[6] = 0.f; }
        __syncthreads();
        for (unsigned i = t; i < M; i += K2_THREADS) {
            unsigned b = g_buf[i];
            if (((b >> 10) & 0x7FFu) == b1) {
                unsigned low = b & 0x3FFu;
                atomicAdd(&cnt[low], 1u);
                atomicAdd(&sum[low], -__logf(__uint_as_float(b)));
            }
        }
        __syncthreads();
        {
            unsigned h[4], local = 0u;
#pragma unroll
            for (int j = 0; j < 4; j++) { h[j] = cnt[t * 4 + j]; local += h[j]; }
            scanS[t] = local;
            __syncthreads();
            for (int off = 1; off < K2_THREADS; off <<= 1) {
                unsigned add = (t >= off) ? scanS[t - off] : 0u;
                __syncthreads();
                scanS[t] += add;
                __syncthreads();
            }
            unsigned incl = scanS[t], excl = incl - local;
            if (r2 >= excl && r2 < incl) {
                unsigned run = excl;
                bool found = false;
#pragma unroll
                for (int j = 0; j < 4; j++) {
                    if (!found) {
                        if (r2 < run + h[j]) { H[3] = t * 4 + j; found = true; }
                        else run += h[j];
                    }
                }
            }
            __syncthreads();
            unsigned b2 = H[3];
            float    s = 0.f; unsigned c = 0u;
#pragma unroll
            for (int j = 0; j < 4; j++)
                if ((unsigned)(t * 4 + j) <= b2) { s += sum[t * 4 + j]; c += h[j]; }   // ties kept
            atomicAdd(&HF[6], s); atomicAdd(&H[5], c);
            __syncthreads();

            if (t == 0) {
                float    sumBound = HF[7] + HF[6];
                unsigned cntBound = H[8] + H[5];
                unsigned kth_bits = (b0 << 21) | (b1 << 10) | b2;
                double   num; unsigned cntk;
                if (keep_all)                  { num = g_sumAll;                  cntk = g_cntAll; }
                else if (kth_bits <= B09_BITS) { num = g_sumB;                    cntk = g_cntB;   }  // threshold = 0.9
                else                           { num = g_sumL + (double)sumBound; cntk = g_cntL + cntBound; }
                unsigned denom = (cntk > 0u) ? cntk : 1u;
                out[0] = (float)(num / (double)denom);
            }
        }

        // ---- reset globals to zero for the next graph replay ----
        __syncthreads();
        for (int i = t; i < 1024; i += K2_THREADS) g_hist[i] = 0u;
        if (t == 0) {
            g_bufcnt = 0u;
            g_sumAll = 0.0; g_sumB = 0.0; g_sumL = 0.0;
            g_cntAll = 0u;  g_cntB = 0u;  g_cntL = 0u;
        }
    }
}

// ---------------- launch ----------------
extern "C" void kernel_launch(void* const* d_in, const int* in_sizes, int n_in,
                              void* d_out, int out_size) {
    const float* pred = (const float*)d_in[0];
    const int*   tgt  = (const int*)d_in[1];
    float*       out  = (float*)d_out;

    compute_kernel<<<K1_BLOCKS, K1_THREADS>>>(pred, tgt);

    int dev = 0, sms = 148, nb = 1;
    cudaGetDevice(&dev);
    cudaDeviceGetAttribute(&sms, cudaDevAttrMultiProcessorCount, dev);
    cudaOccupancyMaxActiveBlocksPerMultiprocessor(&nb, tail_kernel, K2_THREADS, 0);
    if (nb < 1) nb = 1;
    int grid = sms * nb;                 // guaranteed co-resident -> barrier is safe

    tail_kernel<<<grid, K2_THREADS>>>(out);
}

// round 7
// speedup vs baseline: 1.0716x; 1.0368x over previous
#include <cuda_runtime.h>

// ---------------- problem constants (fixed shapes) ----------------
#define C_CLASSES   12
#define LOG_DHW     20                    // d*h*w = 64*128*128 = 2^20
#define DHW         (1u << LOG_DHW)
#define NPIX        (2u * DHW)            // 2,097,152
#define NPIX4       (NPIX / 4u)           // 524,288 uint4 groups
#define MIN_KEPT_K  10000u
#define IGNORE_LBL  255
#define INF_BITS    0x7F800000u
#define B09_BITS    0x3F666666u           // bits of 0.9f (probs >= 0: uint order == float order)

// ---------------- device scratch (zero-init; reset each run) ----------------
__device__ unsigned int g_prob_bits[NPIX];   // prob-at-label bits; INF for invalid
__device__ unsigned int g_hist[1024];        // L0 histogram of bits>>21
__device__ unsigned int g_h1cnt[2048];       // mid-11-bit hist within bin b0
__device__ float        g_h1sum[2048];
__device__ unsigned int g_h2cnt[1024];       // low-10-bit hist within (b0,b1)
__device__ float        g_h2sum[1024];
__device__ double       g_sumAll, g_sumB, g_sumL;
__device__ unsigned int g_cntAll, g_cntB, g_cntL;
__device__ unsigned int g_bar_count;         // self-resetting grid barrier
__device__ unsigned int g_bar_gen;           // monotonic generation

// ==================================================================
// Kernel 1: straight-line CE map + L0 histogram (unchanged from R6:
// ~20.5us @ 5.3 TB/s). One uint4 pixel-group per thread.
// ==================================================================
#define K1_THREADS 256
#define K1_BLOCKS  (NPIX4 / K1_THREADS)   // 2048

__device__ __forceinline__ unsigned int pixel_prob_bits(const float v[C_CLASSES], int l) {
    float m = v[0];
#pragma unroll
    for (int c = 1; c < C_CLASSES; c++) m = fmaxf(m, v[c]);
    float sum = 0.f, xl = 0.f;
#pragma unroll
    for (int c = 0; c < C_CLASSES; c++) {
        sum += __expf(v[c] - m);
        if (c == l) xl = v[c];
    }
    float lp = xl - (m + __logf(sum));
    if (l == IGNORE_LBL) return INF_BITS;      // invalid -> +inf (sorts last, like reference)
    return __float_as_uint(__expf(lp));        // prob in [0,1]
}

__global__ void __launch_bounds__(K1_THREADS)
compute_kernel(const float* __restrict__ pred, const int* __restrict__ tgt) {
    __shared__ unsigned int sh[1024];
    const int t = threadIdx.x;
    for (int i = t; i < 1024; i += K1_THREADS) sh[i] = 0u;
    __syncthreads();

    const unsigned p4 = blockIdx.x * K1_THREADS + t;      // uint4-group index
    const unsigned n  = p4 >> 18;                         // DHW/4 = 2^18 groups per image
    const unsigned s4 = p4 & 0x3FFFFu;
    const float4* base = (const float4*)(pred + (((size_t)n * C_CLASSES) << LOG_DHW)) + s4;

    float4 x[C_CLASSES];
#pragma unroll
    for (int c = 0; c < C_CLASSES; c++)
        x[c] = base[(size_t)c << 18];

    int4 lab = ((const int4*)tgt)[p4];                    // target is int32 (jax x64 disabled)

    float v[C_CLASSES];
    uint4 pb;
#pragma unroll
    for (int c = 0; c < C_CLASSES; c++) v[c] = x[c].x;
    pb.x = pixel_prob_bits(v, lab.x);
#pragma unroll
    for (int c = 0; c < C_CLASSES; c++) v[c] = x[c].y;
    pb.y = pixel_prob_bits(v, lab.y);
#pragma unroll
    for (int c = 0; c < C_CLASSES; c++) v[c] = x[c].z;
    pb.z = pixel_prob_bits(v, lab.z);
#pragma unroll
    for (int c = 0; c < C_CLASSES; c++) v[c] = x[c].w;
    pb.w = pixel_prob_bits(v, lab.w);

    ((uint4*)g_prob_bits)[p4] = pb;

    atomicAdd(&sh[pb.x >> 21], 1u);
    atomicAdd(&sh[pb.y >> 21], 1u);
    atomicAdd(&sh[pb.z >> 21], 1u);
    atomicAdd(&sh[pb.w >> 21], 1u);

    __syncthreads();
    for (int i = t; i < 1024; i += K1_THREADS) {
        unsigned c = sh[i];
        if (c) atomicAdd(&g_hist[i], c);
    }
}

// ==================================================================
// Kernel 2: select + sums + histogram-refined kth + finalize + reset.
// Persistent, occupancy-sized; 2 internal grid barriers. NO compaction.
// ==================================================================
#define K2_THREADS 256

__device__ __forceinline__ void grid_barrier() {
    __syncthreads();
    __threadfence();                                  // release
    if (threadIdx.x == 0) {
        unsigned gen = *(volatile unsigned*)&g_bar_gen;
        unsigned a   = atomicAdd(&g_bar_count, 1u);
        if (a == gridDim.x - 1u) {
            *(volatile unsigned*)&g_bar_count = 0u;
            __threadfence();
            atomicAdd(&g_bar_gen, 1u);
        } else {
            while (*(volatile unsigned*)&g_bar_gen == gen) { }
        }
        __threadfence();                              // acquire
    }
    __syncthreads();
}

// shared layout:
// [0:64)        header H/HF: H[0]=b0 H[1]=r H[2]=keep_all H[3]=b1 H[4]=r2
//                            H[5]=accC HF[6]=accS
// [64:8256)     cntS (2048 u32) / warp-reduce arrays
// [8256:16448)  sumS (2048 f32)
// [16448:17472) scanS (256 u32)
#define SMEM_BYTES 17472

__global__ void __launch_bounds__(K2_THREADS)
tail_kernel(float* __restrict__ out) {
    __shared__ __align__(16) unsigned char S[SMEM_BYTES];
    unsigned* H  = (unsigned*)S;
    float*    HF = (float*)S;
    unsigned* cntS  = (unsigned*)(S + 64);
    float*    sumS  = (float*)(S + 8256);
    unsigned* scanS = (unsigned*)(S + 16448);
    const int t    = threadIdx.x;
    const int bid  = blockIdx.x;
    const int lane = t & 31;
    const unsigned NTH = gridDim.x * K2_THREADS;

    // ----- phase A: every block locates kth L0 bin b0 (g_hist in L2) -----
    {
        unsigned inv       = g_hist[1020];                 // INF_BITS>>21 = 1020
        unsigned num_valid = NPIX - inv;
        unsigned keep_all  = (MIN_KEPT_K >= num_valid) ? 1u : 0u;
        unsigned mk        = (MIN_KEPT_K < num_valid) ? MIN_KEPT_K : num_valid;
        unsigned k         = (mk > 0u) ? (mk - 1u) : 0u;

        unsigned h[4], local = 0u;
#pragma unroll
        for (int i = 0; i < 4; i++) { h[i] = g_hist[t * 4 + i]; local += h[i]; }
        scanS[t] = local;
        __syncthreads();
        for (int off = 1; off < K2_THREADS; off <<= 1) {
            unsigned add = (t >= off) ? scanS[t - off] : 0u;
            __syncthreads();
            scanS[t] += add;
            __syncthreads();
        }
        unsigned incl = scanS[t], excl = incl - local;
        if (k >= excl && k < incl) {
            unsigned run = excl;
            bool found = false;
#pragma unroll
            for (int i = 0; i < 4; i++) {
                if (!found) {
                    if (k < run + h[i]) { H[0] = t * 4 + i; H[1] = k - run; found = true; }
                    else run += h[i];
                }
            }
        }
        if (t == 0) H[2] = keep_all;
        __syncthreads();
    }
    const unsigned b0 = H[0];
    const unsigned r  = H[1];

    // ----- phase B: global sums + mid-11-bit (cnt,sum) hist of bin b0 -----
    {
        for (int i = t; i < 2048; i += K2_THREADS) { cntS[i] = 0u; sumS[i] = 0.f; }
        __syncthreads();

        float    sAll = 0.f, sB = 0.f, sL = 0.f;
        unsigned cAll = 0u,  cB = 0u,  cL = 0u;

        for (unsigned i = bid * K2_THREADS + t; i < NPIX4; i += NTH) {
            uint4 pb = ((const uint4*)g_prob_bits)[i];
            unsigned bs[4] = { pb.x, pb.y, pb.z, pb.w };
#pragma unroll
            for (int j = 0; j < 4; j++) {
                unsigned b = bs[j];
                if (b != INF_BITS) {
                    float nll = -__logf(__uint_as_float(b));
                    cAll++; sAll += nll;
                    if (b <= B09_BITS) { cB++; sB += nll; }
                    unsigned bin = b >> 21;
                    if (bin < b0)       { cL++; sL += nll; }
                    else if (bin == b0) {
                        unsigned mid = (b >> 10) & 0x7FFu;
                        atomicAdd(&cntS[mid], 1u);
                        atomicAdd(&sumS[mid], nll);
                    }
                }
            }
        }

#pragma unroll
        for (int off = 16; off > 0; off >>= 1) {
            sAll += __shfl_down_sync(0xFFFFFFFFu, sAll, off);
            sB   += __shfl_down_sync(0xFFFFFFFFu, sB,   off);
            sL   += __shfl_down_sync(0xFFFFFFFFu, sL,   off);
            cAll += __shfl_down_sync(0xFFFFFFFFu, cAll, off);
            cB   += __shfl_down_sync(0xFFFFFFFFu, cB,   off);
            cL   += __shfl_down_sync(0xFFFFFFFFu, cL,   off);
        }
        float*    ws = (float*)scanS;                 // reuse scan area for warp partials
        unsigned* wc = (unsigned*)scanS + 24;
        int w = t >> 5;
        if (lane == 0) {
            ws[w] = sAll; ws[8 + w] = sB; ws[16 + w] = sL;
            wc[w] = cAll; wc[8 + w] = cB; wc[16 + w] = cL;
        }
        __syncthreads();
        if (t == 0) {
            float    SA = 0.f, SBs = 0.f, SL = 0.f;
            unsigned CA = 0u,  CBc = 0u, CL = 0u;
#pragma unroll
            for (int i = 0; i < 8; i++) {
                SA += ws[i]; SBs += ws[8 + i]; SL += ws[16 + i];
                CA += wc[i]; CBc += wc[8 + i]; CL += wc[16 + i];
            }
            atomicAdd(&g_sumAll, (double)SA);
            atomicAdd(&g_sumB,   (double)SBs);
            atomicAdd(&g_sumL,   (double)SL);
            atomicAdd(&g_cntAll, CA);
            atomicAdd(&g_cntB,   CBc);
            atomicAdd(&g_cntL,   CL);
        }
        // flush shared mid-hist to global (distinct addresses; low contention)
        for (int i = t; i < 2048; i += K2_THREADS) {
            unsigned c = cntS[i];
            if (c) { atomicAdd(&g_h1cnt[i], c); atomicAdd(&g_h1sum[i], sumS[i]); }
        }
    }
    grid_barrier();

    // ----- phase C: every block finds b1/r2 from g_h1cnt; grid rescan fills low hist -----
    {
        unsigned h[8], local = 0u;
#pragma unroll
        for (int j = 0; j < 8; j++) { h[j] = g_h1cnt[t * 8 + j]; local += h[j]; }
        scanS[t] = local;
        __syncthreads();
        for (int off = 1; off < K2_THREADS; off <<= 1) {
            unsigned add = (t >= off) ? scanS[t - off] : 0u;
            __syncthreads();
            scanS[t] += add;
            __syncthreads();
        }
        unsigned incl = scanS[t], excl = incl - local;
        if (r >= excl && r < incl) {
            unsigned run = excl;
            bool found = false;
#pragma unroll
            for (int j = 0; j < 8; j++) {
                if (!found) {
                    if (r < run + h[j]) { H[3] = t * 8 + j; H[4] = r - run; found = true; }
                    else run += h[j];
                }
            }
        }
        __syncthreads();
        const unsigned b1 = H[3];
        const unsigned top22 = (b0 << 11) | b1;

        // rescan prob bits (L2-resident), tally the tiny (b0,b1) subset
        for (unsigned i = bid * K2_THREADS + t; i < NPIX4; i += NTH) {
            uint4 pb = ((const uint4*)g_prob_bits)[i];
            unsigned bs[4] = { pb.x, pb.y, pb.z, pb.w };
#pragma unroll
            for (int j = 0; j < 4; j++) {
                unsigned b = bs[j];
                if ((b >> 10) == top22) {
                    unsigned low = b & 0x3FFu;
                    atomicAdd(&g_h2cnt[low], 1u);
                    atomicAdd(&g_h2sum[low], -__logf(__uint_as_float(b)));
                }
            }
        }
    }
    grid_barrier();

    // ----- phase D: block 0 resolves b2, combines, writes loss, resets state -----
    if (bid != 0) return;
    {
        const unsigned keep_all = H[2];
        const unsigned b1 = H[3], r2 = H[4];

        // sums over mid-bins strictly below b1 (within bin b0)
        if (t == 0) { HF[6] = 0.f; H[5] = 0u; }
        __syncthreads();
        {
            float    s = 0.f; unsigned c = 0u;
#pragma unroll
            for (int j = 0; j < 8; j++) {
                unsigned idx = t * 8 + j;
                if (idx < b1) { s += g_h1sum[idx]; c += g_h1cnt[idx]; }
            }
            atomicAdd(&HF[6], s); atomicAdd(&H[5], c);
        }
        __syncthreads();
        const float    sumBelow1 = HF[6];
        const unsigned cntBelow1 = H[5];
        __syncthreads();

        // find b2 at rank r2 in the low-10-bit hist
        unsigned h[4], local = 0u;
#pragma unroll
        for (int j = 0; j < 4; j++) { h[j] = g_h2cnt[t * 4 + j]; local += h[j]; }
        scanS[t] = local;
        if (t == 0) { H[3] = 0u; HF[6] = 0.f; H[5] = 0u; }
        __syncthreads();
        for (int off = 1; off < K2_THREADS; off <<= 1) {
            unsigned add = (t >= off) ? scanS[t - off] : 0u;
            __syncthreads();
            scanS[t] += add;
            __syncthreads();
        }
        unsigned incl = scanS[t], excl = incl - local;
        if (r2 >= excl && r2 < incl) {
            unsigned run = excl;
            bool found = false;
#pragma unroll
            for (int j = 0; j < 4; j++) {
                if (!found) {
                    if (r2 < run + h[j]) { H[3] = t * 4 + j; found = true; }
                    else run += h[j];
                }
            }
        }
        __syncthreads();
        const unsigned b2 = H[3];
        {
            float    s = 0.f; unsigned c = 0u;
#pragma unroll
            for (int j = 0; j < 4; j++) {
                unsigned idx = t * 4 + j;
                if (idx <= b2) { s += g_h2sum[idx]; c += h[j]; }   // ties at kth all kept
            }
            atomicAdd(&HF[6], s); atomicAdd(&H[5], c);
        }
        __syncthreads();

        if (t == 0) {
            float    sumBound = sumBelow1 + HF[6];
            unsigned cntBound = cntBelow1 + H[5];
            unsigned kth_bits = (b0 << 21) | (b1 << 10) | b2;
            double   num; unsigned cntk;
            if (keep_all)                  { num = g_sumAll;                  cntk = g_cntAll; }
            else if (kth_bits <= B09_BITS) { num = g_sumB;                    cntk = g_cntB;   }  // threshold = 0.9
            else                           { num = g_sumL + (double)sumBound; cntk = g_cntL + cntBound; }
            unsigned denom = (cntk > 0u) ? cntk : 1u;
            out[0] = (float)(num / (double)denom);
        }

        // reset globals for the next graph replay
        __syncthreads();
        for (int i = t; i < 2048; i += K2_THREADS) { g_h1cnt[i] = 0u; g_h1sum[i] = 0.f; }
        for (int i = t; i < 1024; i += K2_THREADS) {
            g_hist[i] = 0u; g_h2cnt[i] = 0u; g_h2sum[i] = 0.f;
        }
        if (t == 0) {
            g_sumAll = 0.0; g_sumB = 0.0; g_sumL = 0.0;
            g_cntAll = 0u;  g_cntB = 0u;  g_cntL = 0u;
        }
    }
}

// ---------------- launch ----------------
extern "C" void kernel_launch(void* const* d_in, const int* in_sizes, int n_in,
                              void* d_out, int out_size) {
    const float* pred = (const float*)d_in[0];
    const int*   tgt  = (const int*)d_in[1];
    float*       out  = (float*)d_out;

    compute_kernel<<<K1_BLOCKS, K1_THREADS>>>(pred, tgt);

    int dev = 0, sms = 148, nb = 1;
    cudaGetDevice(&dev);
    cudaDeviceGetAttribute(&sms, cudaDevAttrMultiProcessorCount, dev);
    cudaOccupancyMaxActiveBlocksPerMultiprocessor(&nb, tail_kernel, K2_THREADS, 0);
    if (nb < 1) nb = 1;
    int grid = sms * nb;                 // guaranteed co-resident -> barrier is safe

    tail_kernel<<<grid, K2_THREADS>>>(out);
}